// round 2
// baseline (speedup 1.0000x reference)
#include <cuda_runtime.h>
#include <cuda_bf16.h>
#include <math.h>

// Problem constants
#define BATCH 8
#define SEQ   1024
#define CDIM  1024
#define NHEAD 16
#define HDIM  64
#define ROWS  (BATCH*SEQ)        // 8192
#define FFDIM (4*CDIM)           // 4096

// ---------------- scratch (static device globals: allocation-free) ----------
__device__ float g_h  [ROWS*CDIM];
__device__ float g_q  [ROWS*CDIM];
__device__ float g_k  [ROWS*CDIM];
__device__ float g_v  [ROWS*CDIM];
__device__ float g_ctx[ROWS*CDIM];
__device__ float g_x1 [ROWS*CDIM];
__device__ float g_h2 [ROWS*CDIM];
__device__ float g_ff1[ROWS*FFDIM];

// ---------------- LayerNorm: one block per row, C=1024 --------------------
__global__ __launch_bounds__(256) void ln_kernel(
    const float* __restrict__ x, const float* __restrict__ w,
    const float* __restrict__ b, float* __restrict__ out)
{
    int row = blockIdx.x;
    int tid = threadIdx.x;
    const float4* xr = (const float4*)(x + (size_t)row * CDIM);
    float4 v = xr[tid];

    float s  = v.x + v.y + v.z + v.w;
    float s2 = v.x*v.x + v.y*v.y + v.z*v.z + v.w*v.w;

    // warp reduce
    #pragma unroll
    for (int o = 16; o > 0; o >>= 1) {
        s  += __shfl_xor_sync(0xffffffff, s,  o);
        s2 += __shfl_xor_sync(0xffffffff, s2, o);
    }
    __shared__ float rs[8], rs2[8];
    int warp = tid >> 5, lane = tid & 31;
    if (lane == 0) { rs[warp] = s; rs2[warp] = s2; }
    __syncthreads();
    if (warp == 0) {
        float a  = (lane < 8) ? rs[lane]  : 0.f;
        float a2 = (lane < 8) ? rs2[lane] : 0.f;
        #pragma unroll
        for (int o = 4; o > 0; o >>= 1) {
            a  += __shfl_xor_sync(0xffffffff, a,  o);
            a2 += __shfl_xor_sync(0xffffffff, a2, o);
        }
        if (lane == 0) { rs[0] = a; rs2[0] = a2; }
    }
    __syncthreads();
    float mu  = rs[0]  * (1.0f / CDIM);
    float var = rs2[0] * (1.0f / CDIM) - mu * mu;
    float inv = rsqrtf(var + 1e-5f);

    float4 wv = ((const float4*)w)[tid];
    float4 bv = ((const float4*)b)[tid];
    float4 o4;
    o4.x = (v.x - mu) * inv * wv.x + bv.x;
    o4.y = (v.y - mu) * inv * wv.y + bv.y;
    o4.z = (v.z - mu) * inv * wv.z + bv.z;
    o4.w = (v.w - mu) * inv * wv.w + bv.w;
    ((float4*)(out + (size_t)row * CDIM))[tid] = o4;
}

// ---------------- SGEMM 128x128x8, 8x8 microtile, fused epilogue -----------
// C[M,N] = A[M,K] @ B[K,N]  (+bias) (GELU) (+res)
template<bool BIAS, bool RES, bool GELU>
__global__ __launch_bounds__(256) void gemm128(
    const float* __restrict__ A, const float* __restrict__ B,
    const float* __restrict__ bias, const float* __restrict__ res,
    float* __restrict__ C, int M, int N, int K)
{
    __shared__ float As[8][128];
    __shared__ float Bs[8][128];

    int tid = threadIdx.x;
    int tx = tid & 15;       // column group
    int ty = tid >> 4;       // row group
    const int m0 = blockIdx.y * 128;
    const int n0 = blockIdx.x * 128;

    float acc[8][8];
    #pragma unroll
    for (int i = 0; i < 8; i++)
        #pragma unroll
        for (int j = 0; j < 8; j++) acc[i][j] = 0.f;

    const int arow = tid >> 1, aseg = tid & 1;
    const int brow = tid >> 5, bcol = (tid & 31) << 2;
    const float* Aptr = A + (size_t)(m0 + arow) * K + aseg * 4;
    const float* Bptr = B + (size_t)brow * N + n0 + bcol;

    for (int k0 = 0; k0 < K; k0 += 8) {
        float4 av = *(const float4*)(Aptr + k0);
        float4 bv = *(const float4*)(Bptr + (size_t)k0 * N);
        __syncthreads();
        As[aseg*4 + 0][arow] = av.x;
        As[aseg*4 + 1][arow] = av.y;
        As[aseg*4 + 2][arow] = av.z;
        As[aseg*4 + 3][arow] = av.w;
        *(float4*)&Bs[brow][bcol] = bv;
        __syncthreads();

        #pragma unroll
        for (int kk = 0; kk < 8; kk++) {
            float a[8], b[8];
            #pragma unroll
            for (int i = 0; i < 8; i++) a[i] = As[kk][ty*8 + i];
            #pragma unroll
            for (int j = 0; j < 8; j++) b[j] = Bs[kk][tx*8 + j];
            #pragma unroll
            for (int i = 0; i < 8; i++)
                #pragma unroll
                for (int j = 0; j < 8; j++)
                    acc[i][j] = fmaf(a[i], b[j], acc[i][j]);
        }
    }

    #pragma unroll
    for (int i = 0; i < 8; i++) {
        int row = m0 + ty*8 + i;
        size_t base = (size_t)row * N + n0 + tx*8;
        #pragma unroll
        for (int j = 0; j < 8; j++) {
            float v = acc[i][j];
            if (BIAS) v += bias[n0 + tx*8 + j];
            if (GELU) v = 0.5f * v * (1.0f + erff(v * 0.70710678118654752f));
            if (RES)  v += res[base + j];
            C[base + j] = v;
        }
    }
}

// ---------------- Flash attention (causal), BQ=64, BKV=32, d=64 ------------
// Q/K/V layout: [B*T, C] with head h at column h*64. Output same layout.
__global__ __launch_bounds__(256) void flash_attn(
    const float* __restrict__ Q, const float* __restrict__ K,
    const float* __restrict__ V, float* __restrict__ O)
{
    const int qt = blockIdx.x;   // query tile (T/64)
    const int h  = blockIdx.y;
    const int b  = blockIdx.z;
    const int tid = threadIdx.x;
    const int r   = tid >> 2;    // query row in tile (0..63)
    const int sub = tid & 3;     // 4 threads per row

    __shared__ float Qs[64][65];
    __shared__ float Ks[32][65];
    __shared__ float Vs[32][65];
    __shared__ float Ps[64][33];

    const size_t rowstride = CDIM;
    const float* Qb = Q + ((size_t)(b*SEQ + qt*64)) * rowstride + h*HDIM;

    // load Q tile: 64x64 floats
    #pragma unroll
    for (int i = tid; i < 64*16; i += 256) {
        int rr = i >> 4; int c4 = (i & 15) << 2;
        float4 v = *(const float4*)(Qb + (size_t)rr * rowstride + c4);
        Qs[rr][c4] = v.x; Qs[rr][c4+1] = v.y; Qs[rr][c4+2] = v.z; Qs[rr][c4+3] = v.w;
    }

    float o[16];
    #pragma unroll
    for (int j = 0; j < 16; j++) o[j] = 0.f;
    float m = -INFINITY, l = 0.f;
    const int qg = qt*64 + r;
    const int nkv = (qt + 1) * 64;

    for (int k0 = 0; k0 < nkv; k0 += 32) {
        __syncthreads();
        // load K,V tiles 32x64
        #pragma unroll
        for (int i = tid; i < 32*16; i += 256) {
            int rr = i >> 4; int c4 = (i & 15) << 2;
            size_t goff = ((size_t)(b*SEQ + k0 + rr)) * rowstride + h*HDIM + c4;
            float4 kv = *(const float4*)(K + goff);
            Ks[rr][c4] = kv.x; Ks[rr][c4+1] = kv.y; Ks[rr][c4+2] = kv.z; Ks[rr][c4+3] = kv.w;
            float4 vv = *(const float4*)(V + goff);
            Vs[rr][c4] = vv.x; Vs[rr][c4+1] = vv.y; Vs[rr][c4+2] = vv.z; Vs[rr][c4+3] = vv.w;
        }
        __syncthreads();

        // scores: this thread does cols sub*8 .. sub*8+7
        float s[8];
        #pragma unroll
        for (int cc = 0; cc < 8; cc++) s[cc] = 0.f;
        #pragma unroll 8
        for (int j = 0; j < 64; j++) {
            float qv = Qs[r][j];
            #pragma unroll
            for (int cc = 0; cc < 8; cc++)
                s[cc] = fmaf(qv, Ks[sub*8 + cc][j], s[cc]);
        }
        float mx = -INFINITY;
        #pragma unroll
        for (int cc = 0; cc < 8; cc++) {
            int cg = k0 + sub*8 + cc;
            s[cc] = (cg <= qg) ? s[cc] * 0.125f : -INFINITY;
            mx = fmaxf(mx, s[cc]);
        }
        mx = fmaxf(mx, __shfl_xor_sync(0xffffffff, mx, 1));
        mx = fmaxf(mx, __shfl_xor_sync(0xffffffff, mx, 2));
        float mnew = fmaxf(m, mx);
        float alpha = __expf(m - mnew);   // m finite after first tile; first tile always valid
        float ssum = 0.f;
        #pragma unroll
        for (int cc = 0; cc < 8; cc++) {
            float p = __expf(s[cc] - mnew);
            Ps[r][sub*8 + cc] = p;
            ssum += p;
        }
        ssum += __shfl_xor_sync(0xffffffff, ssum, 1);
        ssum += __shfl_xor_sync(0xffffffff, ssum, 2);
        l = l * alpha + ssum;
        m = mnew;
        #pragma unroll
        for (int j = 0; j < 16; j++) o[j] *= alpha;
        __syncthreads();

        // O += P @ V ; this thread owns cols sub*16 .. sub*16+15
        #pragma unroll 4
        for (int c = 0; c < 32; c++) {
            float p = Ps[r][c];
            #pragma unroll
            for (int j = 0; j < 16; j++)
                o[j] = fmaf(p, Vs[c][sub*16 + j], o[j]);
        }
    }

    float inv = 1.0f / l;
    float* Optr = O + ((size_t)(b*SEQ + qg)) * rowstride + h*HDIM + sub*16;
    #pragma unroll
    for (int j4 = 0; j4 < 4; j4++) {
        float4 v;
        v.x = o[j4*4+0]*inv; v.y = o[j4*4+1]*inv;
        v.z = o[j4*4+2]*inv; v.w = o[j4*4+3]*inv;
        *(float4*)(Optr + j4*4) = v;
    }
}

// ---------------- launch ----------------------------------------------------
extern "C" void kernel_launch(void* const* d_in, const int* in_sizes, int n_in,
                              void* d_out, int out_size)
{
    const float* x    = (const float*)d_in[0];
    // d_in[1] = mask (tril, int32) -> causal handled analytically
    const float* ln1w = (const float*)d_in[2];
    const float* ln1b = (const float*)d_in[3];
    const float* ln2w = (const float*)d_in[4];
    const float* ln2b = (const float*)d_in[5];
    const float* wq   = (const float*)d_in[6];
    const float* bq   = (const float*)d_in[7];
    const float* wk   = (const float*)d_in[8];
    const float* bk   = (const float*)d_in[9];
    const float* wv   = (const float*)d_in[10];
    const float* bv   = (const float*)d_in[11];
    const float* wo   = (const float*)d_in[12];
    const float* bo   = (const float*)d_in[13];
    const float* w1   = (const float*)d_in[14];
    const float* b1   = (const float*)d_in[15];
    const float* w2   = (const float*)d_in[16];
    const float* b2   = (const float*)d_in[17];
    float* out = (float*)d_out;

    float *h, *q, *k, *v, *ctx, *x1, *h2, *ff1;
    cudaGetSymbolAddress((void**)&h,   g_h);
    cudaGetSymbolAddress((void**)&q,   g_q);
    cudaGetSymbolAddress((void**)&k,   g_k);
    cudaGetSymbolAddress((void**)&v,   g_v);
    cudaGetSymbolAddress((void**)&ctx, g_ctx);
    cudaGetSymbolAddress((void**)&x1,  g_x1);
    cudaGetSymbolAddress((void**)&h2,  g_h2);
    cudaGetSymbolAddress((void**)&ff1, g_ff1);

    dim3 gproj(CDIM/128, ROWS/128);    // (8, 64)
    dim3 gff1 (FFDIM/128, ROWS/128);   // (32, 64)

    // 1) LN1
    ln_kernel<<<ROWS, 256>>>(x, ln1w, ln1b, h);
    // 2) QKV projections
    gemm128<true, false, false><<<gproj, 256>>>(h, wq, bq, nullptr, q, ROWS, CDIM, CDIM);
    gemm128<true, false, false><<<gproj, 256>>>(h, wk, bk, nullptr, k, ROWS, CDIM, CDIM);
    gemm128<true, false, false><<<gproj, 256>>>(h, wv, bv, nullptr, v, ROWS, CDIM, CDIM);
    // 3) causal flash attention
    flash_attn<<<dim3(SEQ/64, NHEAD, BATCH), 256>>>(q, k, v, ctx);
    // 4) output projection + residual
    gemm128<true, true, false><<<gproj, 256>>>(ctx, wo, bo, x, x1, ROWS, CDIM, CDIM);
    // 5) LN2
    ln_kernel<<<ROWS, 256>>>(x1, ln2w, ln2b, h2);
    // 6) FFN up + exact GELU
    gemm128<true, false, true><<<gff1, 256>>>(h2, w1, b1, nullptr, ff1, ROWS, FFDIM, CDIM);
    // 7) FFN down + residual -> output
    gemm128<true, true, false><<<gproj, 256>>>(ff1, w2, b2, x1, out, ROWS, CDIM, FFDIM);
}

// round 4
// speedup vs baseline: 3.2652x; 3.2652x over previous
#include <cuda_runtime.h>
#include <cuda_bf16.h>
#include <math.h>
#include <stdint.h>

// Problem constants
#define BATCH 8
#define SEQ   1024
#define CDIM  1024
#define NHEAD 16
#define HDIM  64
#define ROWS  (BATCH*SEQ)        // 8192
#define FFDIM (4*CDIM)           // 4096

// ======================= PTX helpers (arch-agnostic, sm_80+) ===============
__device__ __forceinline__ uint32_t smem_u32(const void* p) {
    uint32_t a;
    asm("{ .reg .u64 t; cvta.to.shared.u64 t, %1; cvt.u32.u64 %0, t; }" : "=r"(a) : "l"(p));
    return a;
}
#define SWZ128(o) ((o) ^ (((o) >> 3) & 0x70))
#define CP16(dst, src) \
    asm volatile("cp.async.cg.shared.global [%0], [%1], 16;" :: "r"(dst), "l"(src) : "memory")
#define CP_COMMIT() asm volatile("cp.async.commit_group;" ::: "memory")

#define LDSM_X4(r0, r1, r2, r3, addr) \
    asm volatile("ldmatrix.sync.aligned.m8n8.x4.shared.b16 {%0,%1,%2,%3}, [%4];" \
        : "=r"(r0), "=r"(r1), "=r"(r2), "=r"(r3) : "r"(addr))

#define MMA16816(d, a, b) \
    asm volatile("mma.sync.aligned.m16n8k16.row.col.f32.bf16.bf16.f32 " \
        "{%0,%1,%2,%3}, {%4,%5,%6,%7}, {%8,%9}, {%0,%1,%2,%3};" \
        : "+f"((d)[0]), "+f"((d)[1]), "+f"((d)[2]), "+f"((d)[3]) \
        : "r"((a)[0]), "r"((a)[1]), "r"((a)[2]), "r"((a)[3]), "r"((b)[0]), "r"((b)[1]))

// ======================= scratch globals (allocation-free) ==================
__device__ __nv_bfloat16 g_h_hi [ROWS*CDIM];
__device__ __nv_bfloat16 g_h_lo [ROWS*CDIM];
__device__ float         g_q    [ROWS*CDIM];
__device__ float         g_k    [ROWS*CDIM];
__device__ float         g_v    [ROWS*CDIM];
__device__ __nv_bfloat16 g_ctx_hi[ROWS*CDIM];
__device__ __nv_bfloat16 g_ctx_lo[ROWS*CDIM];
__device__ float         g_x1  [ROWS*CDIM];
__device__ __nv_bfloat16 g_h2_hi[ROWS*CDIM];
__device__ __nv_bfloat16 g_h2_lo[ROWS*CDIM];
__device__ __nv_bfloat16 g_ff1_hi[ROWS*FFDIM];
__device__ __nv_bfloat16 g_ff1_lo[ROWS*FFDIM];
// transposed + split weights [N, K]
__device__ __nv_bfloat16 g_wqT_hi[CDIM*CDIM], g_wqT_lo[CDIM*CDIM];
__device__ __nv_bfloat16 g_wkT_hi[CDIM*CDIM], g_wkT_lo[CDIM*CDIM];
__device__ __nv_bfloat16 g_wvT_hi[CDIM*CDIM], g_wvT_lo[CDIM*CDIM];
__device__ __nv_bfloat16 g_woT_hi[CDIM*CDIM], g_woT_lo[CDIM*CDIM];
__device__ __nv_bfloat16 g_w1T_hi[CDIM*FFDIM], g_w1T_lo[CDIM*FFDIM];
__device__ __nv_bfloat16 g_w2T_hi[CDIM*FFDIM], g_w2T_lo[CDIM*FFDIM];

__device__ __forceinline__ void split_bf16(float v, __nv_bfloat16& hi, __nv_bfloat16& lo) {
    hi = __float2bfloat16(v);
    lo = __float2bfloat16(v - __bfloat162float(hi));
}

// ======================= weight transpose + split ===========================
// W[K,N] fp32 -> Wt[N,K] bf16 hi/lo
__global__ __launch_bounds__(256) void wsplitT_kernel(
    const float* __restrict__ W, __nv_bfloat16* __restrict__ hi,
    __nv_bfloat16* __restrict__ lo, int K, int N)
{
    __shared__ float t[32][33];
    int tx = threadIdx.x, ty = threadIdx.y;
    int n0 = blockIdx.x * 32, k0 = blockIdx.y * 32;
    #pragma unroll
    for (int i = 0; i < 4; i++)
        t[ty + 8*i][tx] = W[(size_t)(k0 + ty + 8*i) * N + n0 + tx];
    __syncthreads();
    #pragma unroll
    for (int i = 0; i < 4; i++) {
        float v = t[tx][ty + 8*i];
        __nv_bfloat16 h, l; split_bf16(v, h, l);
        size_t o = (size_t)(n0 + ty + 8*i) * K + k0 + tx;
        hi[o] = h; lo[o] = l;
    }
}

// ======================= LayerNorm -> bf16 split ============================
__global__ __launch_bounds__(256) void ln_kernel(
    const float* __restrict__ x, const float* __restrict__ w,
    const float* __restrict__ b, __nv_bfloat16* __restrict__ ohi,
    __nv_bfloat16* __restrict__ olo)
{
    int row = blockIdx.x;
    int tid = threadIdx.x;
    const float4* xr = (const float4*)(x + (size_t)row * CDIM);
    float4 v = xr[tid];

    float s  = v.x + v.y + v.z + v.w;
    float s2 = v.x*v.x + v.y*v.y + v.z*v.z + v.w*v.w;
    #pragma unroll
    for (int o = 16; o > 0; o >>= 1) {
        s  += __shfl_xor_sync(0xffffffff, s,  o);
        s2 += __shfl_xor_sync(0xffffffff, s2, o);
    }
    __shared__ float rs[8], rs2[8];
    int warp = tid >> 5, lane = tid & 31;
    if (lane == 0) { rs[warp] = s; rs2[warp] = s2; }
    __syncthreads();
    if (warp == 0) {
        float a  = (lane < 8) ? rs[lane]  : 0.f;
        float a2 = (lane < 8) ? rs2[lane] : 0.f;
        #pragma unroll
        for (int o = 4; o > 0; o >>= 1) {
            a  += __shfl_xor_sync(0xffffffff, a,  o);
            a2 += __shfl_xor_sync(0xffffffff, a2, o);
        }
        if (lane == 0) { rs[0] = a; rs2[0] = a2; }
    }
    __syncthreads();
    float mu  = rs[0]  * (1.0f / CDIM);
    float var = rs2[0] * (1.0f / CDIM) - mu * mu;
    float inv = rsqrtf(var + 1e-5f);

    float4 wv = ((const float4*)w)[tid];
    float4 bv = ((const float4*)b)[tid];
    float o0 = (v.x - mu) * inv * wv.x + bv.x;
    float o1 = (v.y - mu) * inv * wv.y + bv.y;
    float o2 = (v.z - mu) * inv * wv.z + bv.z;
    float o3 = (v.w - mu) * inv * wv.w + bv.w;
    size_t base = (size_t)row * CDIM + tid * 4;
    __nv_bfloat162 h01, h23, l01, l23;
    split_bf16(o0, h01.x, l01.x); split_bf16(o1, h01.y, l01.y);
    split_bf16(o2, h23.x, l23.x); split_bf16(o3, h23.y, l23.y);
    *(__nv_bfloat162*)(ohi + base)     = h01;
    *(__nv_bfloat162*)(ohi + base + 2) = h23;
    *(__nv_bfloat162*)(olo + base)     = l01;
    *(__nv_bfloat162*)(olo + base + 2) = l23;
}

// ======================= mma.sync split-bf16 GEMM ===========================
// D[M,N] = A[M,K] @ Wt[N,K]^T ; A,Wt as bf16 hi/lo pairs; fp32 accum regs.
// EPI: 0 = bias -> fp32 ; 1 = bias + res -> fp32 ; 2 = bias + GELU -> bf16 split
// CTA tile 128x128, BK=64 (128B rows SW128), 3-stage cp.async pipeline.
#define STAGE_BYTES 65536
#define NSTAGE 3
#define GEMM_SMEM (NSTAGE*STAGE_BYTES + 1024)

// 128 rows x 64 bf16 (=128B) tile, swizzled, 256 threads
__device__ __forceinline__ void load_tile16(uint32_t sbase, const __nv_bfloat16* g,
                                            int ldk, int kcol, int tid) {
    #pragma unroll
    for (int i = tid; i < 1024; i += 256) {
        int row = i >> 3, seg = i & 7;
        const __nv_bfloat16* src = g + (size_t)row * ldk + kcol + seg * 8;
        uint32_t dst = sbase + SWZ128(row * 128 + seg * 16);
        CP16(dst, src);
    }
}

template<int EPI>
__global__ __launch_bounds__(256, 1) void gemm_mma(
    const __nv_bfloat16* __restrict__ Ahi, const __nv_bfloat16* __restrict__ Alo,
    const __nv_bfloat16* __restrict__ Bhi, const __nv_bfloat16* __restrict__ Blo,
    const float* __restrict__ bias, const float* __restrict__ res,
    float* __restrict__ outF, __nv_bfloat16* __restrict__ outHi,
    __nv_bfloat16* __restrict__ outLo, int K, int N)
{
    extern __shared__ __align__(1024) char smem_raw[];
    uint32_t sb = (smem_u32(smem_raw) + 1023) & ~1023u;
    const int tid = threadIdx.x, lane = tid & 31, wid = tid >> 5;
    const int warpM = wid >> 2, warpN = wid & 3;   // 2 x 4 warp grid
    const int m0 = blockIdx.y * 128, n0 = blockIdx.x * 128;

    const __nv_bfloat16* Ah = Ahi + (size_t)m0 * K;
    const __nv_bfloat16* Al = Alo + (size_t)m0 * K;
    const __nv_bfloat16* Bh = Bhi + (size_t)n0 * K;
    const __nv_bfloat16* Bl = Blo + (size_t)n0 * K;

    float acc[4][4][4];
    #pragma unroll
    for (int mi = 0; mi < 4; mi++)
        #pragma unroll
        for (int ni = 0; ni < 4; ni++)
            #pragma unroll
            for (int r = 0; r < 4; r++) acc[mi][ni][r] = 0.f;

    // per-lane ldmatrix address components
    const int a_r  = (lane & 7) + (((lane >> 3) & 1) << 3);  // row within m16
    const int a_kb = (lane >> 4) * 16;                       // k-half byte offset
    const int b_n  = ((lane >> 4) & 1) * 8 + (lane & 7);     // row within n16
    const int b_kb = ((lane >> 3) & 1) * 16;

    const int chunks = K / 64;
    // prologue: stages 0..2
    #pragma unroll
    for (int c = 0; c < NSTAGE; c++) {
        uint32_t base = sb + c * STAGE_BYTES;
        load_tile16(base,         Ah, K, c*64, tid);
        load_tile16(base + 16384, Al, K, c*64, tid);
        load_tile16(base + 32768, Bh, K, c*64, tid);
        load_tile16(base + 49152, Bl, K, c*64, tid);
        CP_COMMIT();
    }

    for (int c = 0; c < chunks; c++) {
        const int s = c % NSTAGE;
        asm volatile("cp.async.wait_group %0;" :: "n"(NSTAGE-1) : "memory");
        __syncthreads();

        const uint32_t stage = sb + s * STAGE_BYTES;
        #pragma unroll
        for (int kk = 0; kk < 4; kk++) {
            uint32_t ah[4][4], al[4][4];
            #pragma unroll
            for (int mi = 0; mi < 4; mi++) {
                int row = warpM*64 + mi*16 + a_r;
                uint32_t off = SWZ128(row*128 + kk*32 + a_kb);
                LDSM_X4(ah[mi][0], ah[mi][1], ah[mi][2], ah[mi][3], stage + off);
                LDSM_X4(al[mi][0], al[mi][1], al[mi][2], al[mi][3], stage + 16384 + off);
            }
            uint32_t bh[4][2], bl[4][2];
            #pragma unroll
            for (int p = 0; p < 2; p++) {
                int row = warpN*32 + p*16 + b_n;
                uint32_t off = SWZ128(row*128 + kk*32 + b_kb);
                uint32_t r0, r1, r2, r3;
                LDSM_X4(r0, r1, r2, r3, stage + 32768 + off);
                bh[2*p][0] = r0; bh[2*p][1] = r1; bh[2*p+1][0] = r2; bh[2*p+1][1] = r3;
                LDSM_X4(r0, r1, r2, r3, stage + 49152 + off);
                bl[2*p][0] = r0; bl[2*p][1] = r1; bl[2*p+1][0] = r2; bl[2*p+1][1] = r3;
            }
            #pragma unroll
            for (int mi = 0; mi < 4; mi++)
                #pragma unroll
                for (int ni = 0; ni < 4; ni++) {
                    MMA16816(acc[mi][ni], ah[mi], bh[ni]);
                    MMA16816(acc[mi][ni], ah[mi], bl[ni]);
                    MMA16816(acc[mi][ni], al[mi], bh[ni]);
                }
        }
        __syncthreads();
        if (c + NSTAGE < chunks) {
            int cn = c + NSTAGE;
            uint32_t base = sb + s * STAGE_BYTES;
            load_tile16(base,         Ah, K, cn*64, tid);
            load_tile16(base + 16384, Al, K, cn*64, tid);
            load_tile16(base + 32768, Bh, K, cn*64, tid);
            load_tile16(base + 49152, Bl, K, cn*64, tid);
        }
        CP_COMMIT();
    }

    // epilogue: acc[mi][ni] -> rows m0+warpM*64+mi*16+{g,g+8}, cols n0+warpN*32+ni*8+tig*2
    const int g = lane >> 2, tig = lane & 3;
    #pragma unroll
    for (int mi = 0; mi < 4; mi++) {
        #pragma unroll
        for (int half = 0; half < 2; half++) {
            int row = m0 + warpM*64 + mi*16 + g + half*8;
            #pragma unroll
            for (int ni = 0; ni < 4; ni++) {
                int col = n0 + warpN*32 + ni*8 + tig*2;
                float v0 = acc[mi][ni][half*2 + 0] + bias[col];
                float v1 = acc[mi][ni][half*2 + 1] + bias[col + 1];
                size_t o = (size_t)row * N + col;
                if (EPI == 2) {
                    v0 = 0.5f * v0 * (1.0f + erff(v0 * 0.70710678118654752f));
                    v1 = 0.5f * v1 * (1.0f + erff(v1 * 0.70710678118654752f));
                    __nv_bfloat162 h2, l2;
                    split_bf16(v0, h2.x, l2.x); split_bf16(v1, h2.y, l2.y);
                    *(__nv_bfloat162*)(outHi + o) = h2;
                    *(__nv_bfloat162*)(outLo + o) = l2;
                } else {
                    if (EPI == 1) {
                        float2 rv = *(const float2*)(res + o);
                        v0 += rv.x; v1 += rv.y;
                    }
                    float2 ov; ov.x = v0; ov.y = v1;
                    *(float2*)(outF + o) = ov;
                }
            }
        }
    }
}

// ======================= Flash attention (fp32) -> bf16 split ctx ===========
__global__ __launch_bounds__(256) void flash_attn(
    const float* __restrict__ Q, const float* __restrict__ K,
    const float* __restrict__ V, __nv_bfloat16* __restrict__ Ohi,
    __nv_bfloat16* __restrict__ Olo)
{
    const int qt = blockIdx.x;
    const int h  = blockIdx.y;
    const int b  = blockIdx.z;
    const int tid = threadIdx.x;
    const int r   = tid >> 2;
    const int sub = tid & 3;

    __shared__ float Qs[64][65];
    __shared__ float Ks[32][65];
    __shared__ float Vs[32][65];
    __shared__ float Ps[64][33];

    const size_t rowstride = CDIM;
    const float* Qb = Q + ((size_t)(b*SEQ + qt*64)) * rowstride + h*HDIM;

    #pragma unroll
    for (int i = tid; i < 64*16; i += 256) {
        int rr = i >> 4; int c4 = (i & 15) << 2;
        float4 v = *(const float4*)(Qb + (size_t)rr * rowstride + c4);
        Qs[rr][c4] = v.x; Qs[rr][c4+1] = v.y; Qs[rr][c4+2] = v.z; Qs[rr][c4+3] = v.w;
    }

    float o[16];
    #pragma unroll
    for (int j = 0; j < 16; j++) o[j] = 0.f;
    float m = -INFINITY, l = 0.f;
    const int qg = qt*64 + r;
    const int nkv = (qt + 1) * 64;

    for (int k0 = 0; k0 < nkv; k0 += 32) {
        __syncthreads();
        #pragma unroll
        for (int i = tid; i < 32*16; i += 256) {
            int rr = i >> 4; int c4 = (i & 15) << 2;
            size_t goff = ((size_t)(b*SEQ + k0 + rr)) * rowstride + h*HDIM + c4;
            float4 kv = *(const float4*)(K + goff);
            Ks[rr][c4] = kv.x; Ks[rr][c4+1] = kv.y; Ks[rr][c4+2] = kv.z; Ks[rr][c4+3] = kv.w;
            float4 vv = *(const float4*)(V + goff);
            Vs[rr][c4] = vv.x; Vs[rr][c4+1] = vv.y; Vs[rr][c4+2] = vv.z; Vs[rr][c4+3] = vv.w;
        }
        __syncthreads();

        float s[8];
        #pragma unroll
        for (int cc = 0; cc < 8; cc++) s[cc] = 0.f;
        #pragma unroll 8
        for (int j = 0; j < 64; j++) {
            float qv = Qs[r][j];
            #pragma unroll
            for (int cc = 0; cc < 8; cc++)
                s[cc] = fmaf(qv, Ks[sub*8 + cc][j], s[cc]);
        }
        float mx = -INFINITY;
        #pragma unroll
        for (int cc = 0; cc < 8; cc++) {
            int cg = k0 + sub*8 + cc;
            s[cc] = (cg <= qg) ? s[cc] * 0.125f : -INFINITY;
            mx = fmaxf(mx, s[cc]);
        }
        mx = fmaxf(mx, __shfl_xor_sync(0xffffffff, mx, 1));
        mx = fmaxf(mx, __shfl_xor_sync(0xffffffff, mx, 2));
        float mnew = fmaxf(m, mx);
        float alpha = __expf(m - mnew);
        float ssum = 0.f;
        #pragma unroll
        for (int cc = 0; cc < 8; cc++) {
            float p = __expf(s[cc] - mnew);
            Ps[r][sub*8 + cc] = p;
            ssum += p;
        }
        ssum += __shfl_xor_sync(0xffffffff, ssum, 1);
        ssum += __shfl_xor_sync(0xffffffff, ssum, 2);
        l = l * alpha + ssum;
        m = mnew;
        #pragma unroll
        for (int j = 0; j < 16; j++) o[j] *= alpha;
        __syncthreads();

        #pragma unroll 4
        for (int c = 0; c < 32; c++) {
            float p = Ps[r][c];
            #pragma unroll
            for (int j = 0; j < 16; j++)
                o[j] = fmaf(p, Vs[c][sub*16 + j], o[j]);
        }
    }

    float inv = 1.0f / l;
    size_t obase = ((size_t)(b*SEQ + qg)) * rowstride + h*HDIM + sub*16;
    #pragma unroll
    for (int j = 0; j < 16; j += 2) {
        float v0 = o[j] * inv, v1 = o[j+1] * inv;
        __nv_bfloat162 hh, ll;
        split_bf16(v0, hh.x, ll.x); split_bf16(v1, hh.y, ll.y);
        *(__nv_bfloat162*)(Ohi + obase + j) = hh;
        *(__nv_bfloat162*)(Olo + obase + j) = ll;
    }
}

// ======================= launch ============================================
extern "C" void kernel_launch(void* const* d_in, const int* in_sizes, int n_in,
                              void* d_out, int out_size)
{
    const float* x    = (const float*)d_in[0];
    const float* ln1w = (const float*)d_in[2];
    const float* ln1b = (const float*)d_in[3];
    const float* ln2w = (const float*)d_in[4];
    const float* ln2b = (const float*)d_in[5];
    const float* wq   = (const float*)d_in[6];
    const float* bq   = (const float*)d_in[7];
    const float* wk   = (const float*)d_in[8];
    const float* bk   = (const float*)d_in[9];
    const float* wv   = (const float*)d_in[10];
    const float* bv   = (const float*)d_in[11];
    const float* wo   = (const float*)d_in[12];
    const float* bo   = (const float*)d_in[13];
    const float* w1   = (const float*)d_in[14];
    const float* b1   = (const float*)d_in[15];
    const float* w2   = (const float*)d_in[16];
    const float* b2   = (const float*)d_in[17];
    float* out = (float*)d_out;

    __nv_bfloat16 *hhi, *hlo, *ctxhi, *ctxlo, *h2hi, *h2lo, *ff1hi, *ff1lo;
    __nv_bfloat16 *wqh, *wql, *wkh, *wkl, *wvh, *wvl, *woh, *wol, *w1h, *w1l, *w2h, *w2l;
    float *q, *k, *v, *x1;
    cudaGetSymbolAddress((void**)&hhi, g_h_hi);   cudaGetSymbolAddress((void**)&hlo, g_h_lo);
    cudaGetSymbolAddress((void**)&q,   g_q);      cudaGetSymbolAddress((void**)&k,   g_k);
    cudaGetSymbolAddress((void**)&v,   g_v);
    cudaGetSymbolAddress((void**)&ctxhi, g_ctx_hi); cudaGetSymbolAddress((void**)&ctxlo, g_ctx_lo);
    cudaGetSymbolAddress((void**)&x1,  g_x1);
    cudaGetSymbolAddress((void**)&h2hi, g_h2_hi); cudaGetSymbolAddress((void**)&h2lo, g_h2_lo);
    cudaGetSymbolAddress((void**)&ff1hi, g_ff1_hi); cudaGetSymbolAddress((void**)&ff1lo, g_ff1_lo);
    cudaGetSymbolAddress((void**)&wqh, g_wqT_hi); cudaGetSymbolAddress((void**)&wql, g_wqT_lo);
    cudaGetSymbolAddress((void**)&wkh, g_wkT_hi); cudaGetSymbolAddress((void**)&wkl, g_wkT_lo);
    cudaGetSymbolAddress((void**)&wvh, g_wvT_hi); cudaGetSymbolAddress((void**)&wvl, g_wvT_lo);
    cudaGetSymbolAddress((void**)&woh, g_woT_hi); cudaGetSymbolAddress((void**)&wol, g_woT_lo);
    cudaGetSymbolAddress((void**)&w1h, g_w1T_hi); cudaGetSymbolAddress((void**)&w1l, g_w1T_lo);
    cudaGetSymbolAddress((void**)&w2h, g_w2T_hi); cudaGetSymbolAddress((void**)&w2l, g_w2T_lo);

    cudaFuncSetAttribute(gemm_mma<0>, cudaFuncAttributeMaxDynamicSharedMemorySize, GEMM_SMEM);
    cudaFuncSetAttribute(gemm_mma<1>, cudaFuncAttributeMaxDynamicSharedMemorySize, GEMM_SMEM);
    cudaFuncSetAttribute(gemm_mma<2>, cudaFuncAttributeMaxDynamicSharedMemorySize, GEMM_SMEM);

    dim3 tb(32, 8);
    // weight transpose + split
    wsplitT_kernel<<<dim3(CDIM/32, CDIM/32), tb>>>(wq, wqh, wql, CDIM, CDIM);
    wsplitT_kernel<<<dim3(CDIM/32, CDIM/32), tb>>>(wk, wkh, wkl, CDIM, CDIM);
    wsplitT_kernel<<<dim3(CDIM/32, CDIM/32), tb>>>(wv, wvh, wvl, CDIM, CDIM);
    wsplitT_kernel<<<dim3(CDIM/32, CDIM/32), tb>>>(wo, woh, wol, CDIM, CDIM);
    wsplitT_kernel<<<dim3(FFDIM/32, CDIM/32), tb>>>(w1, w1h, w1l, CDIM, FFDIM);
    wsplitT_kernel<<<dim3(CDIM/32, FFDIM/32), tb>>>(w2, w2h, w2l, FFDIM, CDIM);

    dim3 gproj(CDIM/128, ROWS/128);    // (8, 64)
    dim3 gff1 (FFDIM/128, ROWS/128);   // (32, 64)

    // 1) LN1 -> h (bf16 split)
    ln_kernel<<<ROWS, 256>>>(x, ln1w, ln1b, hhi, hlo);
    // 2) QKV (fp32 out)
    gemm_mma<0><<<gproj, 256, GEMM_SMEM>>>(hhi, hlo, wqh, wql, bq, nullptr, q, nullptr, nullptr, CDIM, CDIM);
    gemm_mma<0><<<gproj, 256, GEMM_SMEM>>>(hhi, hlo, wkh, wkl, bk, nullptr, k, nullptr, nullptr, CDIM, CDIM);
    gemm_mma<0><<<gproj, 256, GEMM_SMEM>>>(hhi, hlo, wvh, wvl, bv, nullptr, v, nullptr, nullptr, CDIM, CDIM);
    // 3) attention -> ctx (bf16 split)
    flash_attn<<<dim3(SEQ/64, NHEAD, BATCH), 256>>>(q, k, v, ctxhi, ctxlo);
    // 4) O-proj + residual -> x1 (fp32)
    gemm_mma<1><<<gproj, 256, GEMM_SMEM>>>(ctxhi, ctxlo, woh, wol, bo, x, x1, nullptr, nullptr, CDIM, CDIM);
    // 5) LN2 -> h2 (bf16 split)
    ln_kernel<<<ROWS, 256>>>(x1, ln2w, ln2b, h2hi, h2lo);
    // 6) FFN1 + GELU -> ff1 (bf16 split)
    gemm_mma<2><<<gff1, 256, GEMM_SMEM>>>(h2hi, h2lo, w1h, w1l, b1, nullptr, nullptr, ff1hi, ff1lo, CDIM, FFDIM);
    // 7) FFN2 + residual -> out (fp32)
    gemm_mma<1><<<gproj, 256, GEMM_SMEM>>>(ff1hi, ff1lo, w2h, w2l, b2, x1, out, nullptr, nullptr, FFDIM, CDIM);
}

// round 5
// speedup vs baseline: 6.3785x; 1.9535x over previous
#include <cuda_runtime.h>
#include <cuda_bf16.h>
#include <math.h>
#include <stdint.h>

// Problem constants
#define BATCH 8
#define SEQ   1024
#define CDIM  1024
#define NHEAD 16
#define HDIM  64
#define ROWS  (BATCH*SEQ)        // 8192
#define FFDIM (4*CDIM)           // 4096

// ======================= PTX helpers (arch-agnostic, sm_80+) ===============
__device__ __forceinline__ uint32_t smem_u32(const void* p) {
    uint32_t a;
    asm("{ .reg .u64 t; cvta.to.shared.u64 t, %1; cvt.u32.u64 %0, t; }" : "=r"(a) : "l"(p));
    return a;
}
#define SWZ128(o) ((o) ^ (((o) >> 3) & 0x70))
#define CP16(dst, src) \
    asm volatile("cp.async.cg.shared.global [%0], [%1], 16;" :: "r"(dst), "l"(src) : "memory")
#define CP_COMMIT() asm volatile("cp.async.commit_group;" ::: "memory")

#define LDSM_X4(r0, r1, r2, r3, addr) \
    asm volatile("ldmatrix.sync.aligned.m8n8.x4.shared.b16 {%0,%1,%2,%3}, [%4];" \
        : "=r"(r0), "=r"(r1), "=r"(r2), "=r"(r3) : "r"(addr))

#define LDSM_X4_TRANS(r0, r1, r2, r3, addr) \
    asm volatile("ldmatrix.sync.aligned.m8n8.x4.trans.shared.b16 {%0,%1,%2,%3}, [%4];" \
        : "=r"(r0), "=r"(r1), "=r"(r2), "=r"(r3) : "r"(addr))

#define MMA16816(d, a, b) \
    asm volatile("mma.sync.aligned.m16n8k16.row.col.f32.bf16.bf16.f32 " \
        "{%0,%1,%2,%3}, {%4,%5,%6,%7}, {%8,%9}, {%0,%1,%2,%3};" \
        : "+f"((d)[0]), "+f"((d)[1]), "+f"((d)[2]), "+f"((d)[3]) \
        : "r"((a)[0]), "r"((a)[1]), "r"((a)[2]), "r"((a)[3]), "r"((b)[0]), "r"((b)[1]))

__device__ __forceinline__ uint32_t pack2bf(float e0, float e1) {
    uint32_t r;
    asm("cvt.rn.bf16x2.f32 %0, %1, %2;" : "=r"(r) : "f"(e1), "f"(e0));
    return r;
}

// ======================= scratch globals (allocation-free) ==================
__device__ __nv_bfloat16 g_h_hi [ROWS*CDIM];
__device__ __nv_bfloat16 g_h_lo [ROWS*CDIM];
__device__ __nv_bfloat16 g_q_hi [ROWS*CDIM], g_q_lo [ROWS*CDIM];
__device__ __nv_bfloat16 g_k_hi [ROWS*CDIM], g_k_lo [ROWS*CDIM];
__device__ __nv_bfloat16 g_v_hi [ROWS*CDIM], g_v_lo [ROWS*CDIM];
__device__ __nv_bfloat16 g_ctx_hi[ROWS*CDIM];
__device__ __nv_bfloat16 g_ctx_lo[ROWS*CDIM];
__device__ float         g_x1  [ROWS*CDIM];
__device__ __nv_bfloat16 g_h2_hi[ROWS*CDIM];
__device__ __nv_bfloat16 g_h2_lo[ROWS*CDIM];
__device__ __nv_bfloat16 g_ff1_hi[ROWS*FFDIM];
__device__ __nv_bfloat16 g_ff1_lo[ROWS*FFDIM];
// transposed + split weights [N, K]
__device__ __nv_bfloat16 g_wqT_hi[CDIM*CDIM], g_wqT_lo[CDIM*CDIM];
__device__ __nv_bfloat16 g_wkT_hi[CDIM*CDIM], g_wkT_lo[CDIM*CDIM];
__device__ __nv_bfloat16 g_wvT_hi[CDIM*CDIM], g_wvT_lo[CDIM*CDIM];
__device__ __nv_bfloat16 g_woT_hi[CDIM*CDIM], g_woT_lo[CDIM*CDIM];
__device__ __nv_bfloat16 g_w1T_hi[CDIM*FFDIM], g_w1T_lo[CDIM*FFDIM];
__device__ __nv_bfloat16 g_w2T_hi[CDIM*FFDIM], g_w2T_lo[CDIM*FFDIM];

__device__ __forceinline__ void split_bf16(float v, __nv_bfloat16& hi, __nv_bfloat16& lo) {
    hi = __float2bfloat16(v);
    lo = __float2bfloat16(v - __bfloat162float(hi));
}

// ======================= weight transpose + split ===========================
__global__ __launch_bounds__(256) void wsplitT_kernel(
    const float* __restrict__ W, __nv_bfloat16* __restrict__ hi,
    __nv_bfloat16* __restrict__ lo, int K, int N)
{
    __shared__ float t[32][33];
    int tx = threadIdx.x, ty = threadIdx.y;
    int n0 = blockIdx.x * 32, k0 = blockIdx.y * 32;
    #pragma unroll
    for (int i = 0; i < 4; i++)
        t[ty + 8*i][tx] = W[(size_t)(k0 + ty + 8*i) * N + n0 + tx];
    __syncthreads();
    #pragma unroll
    for (int i = 0; i < 4; i++) {
        float v = t[tx][ty + 8*i];
        __nv_bfloat16 h, l; split_bf16(v, h, l);
        size_t o = (size_t)(n0 + ty + 8*i) * K + k0 + tx;
        hi[o] = h; lo[o] = l;
    }
}

// ======================= LayerNorm -> bf16 split ============================
__global__ __launch_bounds__(256) void ln_kernel(
    const float* __restrict__ x, const float* __restrict__ w,
    const float* __restrict__ b, __nv_bfloat16* __restrict__ ohi,
    __nv_bfloat16* __restrict__ olo)
{
    int row = blockIdx.x;
    int tid = threadIdx.x;
    const float4* xr = (const float4*)(x + (size_t)row * CDIM);
    float4 v = xr[tid];

    float s  = v.x + v.y + v.z + v.w;
    float s2 = v.x*v.x + v.y*v.y + v.z*v.z + v.w*v.w;
    #pragma unroll
    for (int o = 16; o > 0; o >>= 1) {
        s  += __shfl_xor_sync(0xffffffff, s,  o);
        s2 += __shfl_xor_sync(0xffffffff, s2, o);
    }
    __shared__ float rs[8], rs2[8];
    int warp = tid >> 5, lane = tid & 31;
    if (lane == 0) { rs[warp] = s; rs2[warp] = s2; }
    __syncthreads();
    if (warp == 0) {
        float a  = (lane < 8) ? rs[lane]  : 0.f;
        float a2 = (lane < 8) ? rs2[lane] : 0.f;
        #pragma unroll
        for (int o = 4; o > 0; o >>= 1) {
            a  += __shfl_xor_sync(0xffffffff, a,  o);
            a2 += __shfl_xor_sync(0xffffffff, a2, o);
        }
        if (lane == 0) { rs[0] = a; rs2[0] = a2; }
    }
    __syncthreads();
    float mu  = rs[0]  * (1.0f / CDIM);
    float var = rs2[0] * (1.0f / CDIM) - mu * mu;
    float inv = rsqrtf(var + 1e-5f);

    float4 wv = ((const float4*)w)[tid];
    float4 bv = ((const float4*)b)[tid];
    float o0 = (v.x - mu) * inv * wv.x + bv.x;
    float o1 = (v.y - mu) * inv * wv.y + bv.y;
    float o2 = (v.z - mu) * inv * wv.z + bv.z;
    float o3 = (v.w - mu) * inv * wv.w + bv.w;
    size_t base = (size_t)row * CDIM + tid * 4;
    __nv_bfloat162 h01, h23, l01, l23;
    split_bf16(o0, h01.x, l01.x); split_bf16(o1, h01.y, l01.y);
    split_bf16(o2, h23.x, l23.x); split_bf16(o3, h23.y, l23.y);
    *(__nv_bfloat162*)(ohi + base)     = h01;
    *(__nv_bfloat162*)(ohi + base + 2) = h23;
    *(__nv_bfloat162*)(olo + base)     = l01;
    *(__nv_bfloat162*)(olo + base + 2) = l23;
}

// ======================= mma.sync split-bf16 GEMM ===========================
// D[M,N] = A[M,K] @ Wt[N,K]^T ; A,Wt as bf16 hi/lo pairs; fp32 accum regs.
// EPI: 0 = bias -> fp32 ; 1 = bias + res -> fp32 ; 2 = bias + GELU -> bf16 split
//      3 = bias -> bf16 split
#define STAGE_BYTES 65536
#define NSTAGE 3
#define GEMM_SMEM (NSTAGE*STAGE_BYTES + 1024)

__device__ __forceinline__ void load_tile16(uint32_t sbase, const __nv_bfloat16* g,
                                            int ldk, int kcol, int tid) {
    #pragma unroll
    for (int i = tid; i < 1024; i += 256) {
        int row = i >> 3, seg = i & 7;
        const __nv_bfloat16* src = g + (size_t)row * ldk + kcol + seg * 8;
        uint32_t dst = sbase + SWZ128(row * 128 + seg * 16);
        CP16(dst, src);
    }
}

template<int EPI>
__global__ __launch_bounds__(256, 1) void gemm_mma(
    const __nv_bfloat16* __restrict__ Ahi, const __nv_bfloat16* __restrict__ Alo,
    const __nv_bfloat16* __restrict__ Bhi, const __nv_bfloat16* __restrict__ Blo,
    const float* __restrict__ bias, const float* __restrict__ res,
    float* __restrict__ outF, __nv_bfloat16* __restrict__ outHi,
    __nv_bfloat16* __restrict__ outLo, int K, int N)
{
    extern __shared__ __align__(1024) char smem_raw[];
    uint32_t sb = (smem_u32(smem_raw) + 1023) & ~1023u;
    const int tid = threadIdx.x, lane = tid & 31, wid = tid >> 5;
    const int warpM = wid >> 2, warpN = wid & 3;   // 2 x 4 warp grid
    const int m0 = blockIdx.y * 128, n0 = blockIdx.x * 128;

    const __nv_bfloat16* Ah = Ahi + (size_t)m0 * K;
    const __nv_bfloat16* Al = Alo + (size_t)m0 * K;
    const __nv_bfloat16* Bh = Bhi + (size_t)n0 * K;
    const __nv_bfloat16* Bl = Blo + (size_t)n0 * K;

    float acc[4][4][4];
    #pragma unroll
    for (int mi = 0; mi < 4; mi++)
        #pragma unroll
        for (int ni = 0; ni < 4; ni++)
            #pragma unroll
            for (int r = 0; r < 4; r++) acc[mi][ni][r] = 0.f;

    const int a_r  = (lane & 7) + (((lane >> 3) & 1) << 3);
    const int a_kb = (lane >> 4) * 16;
    const int b_n  = ((lane >> 4) & 1) * 8 + (lane & 7);
    const int b_kb = ((lane >> 3) & 1) * 16;

    const int chunks = K / 64;
    #pragma unroll
    for (int c = 0; c < NSTAGE; c++) {
        uint32_t base = sb + c * STAGE_BYTES;
        load_tile16(base,         Ah, K, c*64, tid);
        load_tile16(base + 16384, Al, K, c*64, tid);
        load_tile16(base + 32768, Bh, K, c*64, tid);
        load_tile16(base + 49152, Bl, K, c*64, tid);
        CP_COMMIT();
    }

    for (int c = 0; c < chunks; c++) {
        const int s = c % NSTAGE;
        asm volatile("cp.async.wait_group %0;" :: "n"(NSTAGE-1) : "memory");
        __syncthreads();

        const uint32_t stage = sb + s * STAGE_BYTES;
        #pragma unroll
        for (int kk = 0; kk < 4; kk++) {
            uint32_t ah[4][4], al[4][4];
            #pragma unroll
            for (int mi = 0; mi < 4; mi++) {
                int row = warpM*64 + mi*16 + a_r;
                uint32_t off = SWZ128(row*128 + kk*32 + a_kb);
                LDSM_X4(ah[mi][0], ah[mi][1], ah[mi][2], ah[mi][3], stage + off);
                LDSM_X4(al[mi][0], al[mi][1], al[mi][2], al[mi][3], stage + 16384 + off);
            }
            uint32_t bh[4][2], bl[4][2];
            #pragma unroll
            for (int p = 0; p < 2; p++) {
                int row = warpN*32 + p*16 + b_n;
                uint32_t off = SWZ128(row*128 + kk*32 + b_kb);
                uint32_t r0, r1, r2, r3;
                LDSM_X4(r0, r1, r2, r3, stage + 32768 + off);
                bh[2*p][0] = r0; bh[2*p][1] = r1; bh[2*p+1][0] = r2; bh[2*p+1][1] = r3;
                LDSM_X4(r0, r1, r2, r3, stage + 49152 + off);
                bl[2*p][0] = r0; bl[2*p][1] = r1; bl[2*p+1][0] = r2; bl[2*p+1][1] = r3;
            }
            #pragma unroll
            for (int mi = 0; mi < 4; mi++)
                #pragma unroll
                for (int ni = 0; ni < 4; ni++) {
                    MMA16816(acc[mi][ni], ah[mi], bh[ni]);
                    MMA16816(acc[mi][ni], ah[mi], bl[ni]);
                    MMA16816(acc[mi][ni], al[mi], bh[ni]);
                }
        }
        __syncthreads();
        if (c + NSTAGE < chunks) {
            int cn = c + NSTAGE;
            uint32_t base = sb + s * STAGE_BYTES;
            load_tile16(base,         Ah, K, cn*64, tid);
            load_tile16(base + 16384, Al, K, cn*64, tid);
            load_tile16(base + 32768, Bh, K, cn*64, tid);
            load_tile16(base + 49152, Bl, K, cn*64, tid);
        }
        CP_COMMIT();
    }

    const int g = lane >> 2, tig = lane & 3;
    #pragma unroll
    for (int mi = 0; mi < 4; mi++) {
        #pragma unroll
        for (int half = 0; half < 2; half++) {
            int row = m0 + warpM*64 + mi*16 + g + half*8;
            #pragma unroll
            for (int ni = 0; ni < 4; ni++) {
                int col = n0 + warpN*32 + ni*8 + tig*2;
                float v0 = acc[mi][ni][half*2 + 0] + bias[col];
                float v1 = acc[mi][ni][half*2 + 1] + bias[col + 1];
                size_t o = (size_t)row * N + col;
                if (EPI == 2 || EPI == 3) {
                    if (EPI == 2) {
                        v0 = 0.5f * v0 * (1.0f + erff(v0 * 0.70710678118654752f));
                        v1 = 0.5f * v1 * (1.0f + erff(v1 * 0.70710678118654752f));
                    }
                    __nv_bfloat162 h2, l2;
                    split_bf16(v0, h2.x, l2.x); split_bf16(v1, h2.y, l2.y);
                    *(__nv_bfloat162*)(outHi + o) = h2;
                    *(__nv_bfloat162*)(outLo + o) = l2;
                } else {
                    if (EPI == 1) {
                        float2 rv = *(const float2*)(res + o);
                        v0 += rv.x; v1 += rv.y;
                    }
                    float2 ov; ov.x = v0; ov.y = v1;
                    *(float2*)(outF + o) = ov;
                }
            }
        }
    }
}

// ======================= Tensor-core flash attention ========================
// CTA: 64 q rows x one head. 4 warps x 16 rows. KV tiles of 64, 2-stage pipe.
// q/k/v are bf16 hi/lo [ROWS, CDIM]; output ctx bf16 hi/lo.
#define ATT_SMEM (16384 + 2*32768)

__device__ __forceinline__ void load_rows64(uint32_t sbase, const __nv_bfloat16* g, int tid) {
    #pragma unroll
    for (int i = tid; i < 512; i += 128) {
        int row = i >> 3, seg = i & 7;
        CP16(sbase + SWZ128(row * 128 + seg * 16), g + (size_t)row * CDIM + seg * 8);
    }
}

__device__ __forceinline__ void mk_pfrag(float e, float o2, uint32_t& hi, uint32_t& lo) {
    float he = __bfloat162float(__float2bfloat16(e));
    float ho = __bfloat162float(__float2bfloat16(o2));
    hi = pack2bf(he, ho);
    lo = pack2bf(e - he, o2 - ho);
}

__global__ __launch_bounds__(128, 2) void flash_attn_tc(
    const __nv_bfloat16* __restrict__ Qhi, const __nv_bfloat16* __restrict__ Qlo,
    const __nv_bfloat16* __restrict__ Khi, const __nv_bfloat16* __restrict__ Klo,
    const __nv_bfloat16* __restrict__ Vhi, const __nv_bfloat16* __restrict__ Vlo,
    __nv_bfloat16* __restrict__ Ohi, __nv_bfloat16* __restrict__ Olo)
{
    extern __shared__ __align__(1024) char smem_raw[];
    uint32_t sb = smem_u32(smem_raw);
    const int qt = blockIdx.x, h = blockIdx.y, b = blockIdx.z;
    const int tid = threadIdx.x, lane = tid & 31, wid = tid >> 5;

    const uint32_t sQh = sb, sQl = sb + 8192;
    const uint32_t sStage = sb + 16384;     // per stage: Khi, Klo, Vhi, Vlo @ +0,+8192,+16384,+24576

    const size_t hoff = (size_t)h * HDIM;
    const size_t qbase = (size_t)(b*SEQ + qt*64);
    load_rows64(sQh, Qhi + qbase*CDIM + hoff, tid);
    load_rows64(sQl, Qlo + qbase*CDIM + hoff, tid);
    CP_COMMIT();

    const __nv_bfloat16* kb_h = Khi + (size_t)b*SEQ*CDIM + hoff;
    const __nv_bfloat16* kb_l = Klo + (size_t)b*SEQ*CDIM + hoff;
    const __nv_bfloat16* vb_h = Vhi + (size_t)b*SEQ*CDIM + hoff;
    const __nv_bfloat16* vb_l = Vlo + (size_t)b*SEQ*CDIM + hoff;

    // stage 0 <- kv tile 0
    load_rows64(sStage,         kb_h, tid);
    load_rows64(sStage +  8192, kb_l, tid);
    load_rows64(sStage + 16384, vb_h, tid);
    load_rows64(sStage + 24576, vb_l, tid);
    CP_COMMIT();

    asm volatile("cp.async.wait_group 1;" ::: "memory");
    __syncthreads();

    const int a_r  = (lane & 7) + (((lane >> 3) & 1) << 3);
    const int a_kb = (lane >> 4) * 16;
    const int b_n  = ((lane >> 4) & 1) * 8 + (lane & 7);
    const int b_kb = ((lane >> 3) & 1) * 16;

    // Q fragments (resident for whole kernel)
    uint32_t qh[4][4], ql[4][4];
    #pragma unroll
    for (int kk = 0; kk < 4; kk++) {
        uint32_t off = SWZ128((wid*16 + a_r)*128 + kk*32 + a_kb);
        LDSM_X4(qh[kk][0], qh[kk][1], qh[kk][2], qh[kk][3], sQh + off);
        LDSM_X4(ql[kk][0], ql[kk][1], ql[kk][2], ql[kk][3], sQl + off);
    }

    float o[8][4];
    #pragma unroll
    for (int ni = 0; ni < 8; ni++)
        #pragma unroll
        for (int j = 0; j < 4; j++) o[ni][j] = 0.f;
    float m0 = -INFINITY, m1 = -INFINITY, l0 = 0.f, l1 = 0.f;
    const int g = lane >> 2, tig = lane & 3;
    const int kvb = (lane & 7) + ((lane >> 3) & 1) * 8;
    const int cbB = ((lane >> 4) & 1) * 16;

    for (int t = 0; t <= qt; t++) {
        asm volatile("cp.async.wait_group 0;" ::: "memory");
        __syncthreads();
        const uint32_t st = sStage + (t & 1) * 32768;
        if (t < qt) {
            uint32_t sn = sStage + ((t + 1) & 1) * 32768;
            size_t roff = (size_t)(t + 1) * 64 * CDIM;
            load_rows64(sn,         kb_h + roff, tid);
            load_rows64(sn +  8192, kb_l + roff, tid);
            load_rows64(sn + 16384, vb_h + roff, tid);
            load_rows64(sn + 24576, vb_l + roff, tid);
            CP_COMMIT();
        }

        // ---- S = Q K^T (split, 3 passes) ----
        float s[8][4];
        #pragma unroll
        for (int ni = 0; ni < 8; ni++)
            #pragma unroll
            for (int j = 0; j < 4; j++) s[ni][j] = 0.f;

        #pragma unroll
        for (int kk = 0; kk < 4; kk++) {
            #pragma unroll
            for (int p = 0; p < 4; p++) {
                uint32_t off = SWZ128((p*16 + b_n)*128 + kk*32 + b_kb);
                uint32_t h0,h1,h2,h3, u0,u1,u2,u3;
                LDSM_X4(h0, h1, h2, h3, st + off);
                LDSM_X4(u0, u1, u2, u3, st + 8192 + off);
                uint32_t bh0[2] = {h0, h1}, bh1[2] = {h2, h3};
                uint32_t bl0[2] = {u0, u1}, bl1[2] = {u2, u3};
                MMA16816(s[2*p],   qh[kk], bh0);
                MMA16816(s[2*p],   qh[kk], bl0);
                MMA16816(s[2*p],   ql[kk], bh0);
                MMA16816(s[2*p+1], qh[kk], bh1);
                MMA16816(s[2*p+1], qh[kk], bl1);
                MMA16816(s[2*p+1], ql[kk], bh1);
            }
        }

        // ---- scale + causal mask ----
        #pragma unroll
        for (int ni = 0; ni < 8; ni++)
            #pragma unroll
            for (int j = 0; j < 4; j++) s[ni][j] *= 0.125f;
        if (t == qt) {
            int r0 = wid*16 + g, r1 = r0 + 8;
            #pragma unroll
            for (int ni = 0; ni < 8; ni++) {
                int c = ni*8 + tig*2;
                if (c     > r0) s[ni][0] = -INFINITY;
                if (c + 1 > r0) s[ni][1] = -INFINITY;
                if (c     > r1) s[ni][2] = -INFINITY;
                if (c + 1 > r1) s[ni][3] = -INFINITY;
            }
        }

        // ---- online softmax ----
        float mx0 = -INFINITY, mx1 = -INFINITY;
        #pragma unroll
        for (int ni = 0; ni < 8; ni++) {
            mx0 = fmaxf(mx0, fmaxf(s[ni][0], s[ni][1]));
            mx1 = fmaxf(mx1, fmaxf(s[ni][2], s[ni][3]));
        }
        mx0 = fmaxf(mx0, __shfl_xor_sync(0xffffffff, mx0, 1));
        mx0 = fmaxf(mx0, __shfl_xor_sync(0xffffffff, mx0, 2));
        mx1 = fmaxf(mx1, __shfl_xor_sync(0xffffffff, mx1, 1));
        mx1 = fmaxf(mx1, __shfl_xor_sync(0xffffffff, mx1, 2));
        float mn0 = fmaxf(m0, mx0), mn1 = fmaxf(m1, mx1);
        float al0 = __expf(m0 - mn0), al1 = __expf(m1 - mn1);
        float sum0 = 0.f, sum1 = 0.f;
        #pragma unroll
        for (int ni = 0; ni < 8; ni++) {
            s[ni][0] = __expf(s[ni][0] - mn0); sum0 += s[ni][0];
            s[ni][1] = __expf(s[ni][1] - mn0); sum0 += s[ni][1];
            s[ni][2] = __expf(s[ni][2] - mn1); sum1 += s[ni][2];
            s[ni][3] = __expf(s[ni][3] - mn1); sum1 += s[ni][3];
        }
        sum0 += __shfl_xor_sync(0xffffffff, sum0, 1);
        sum0 += __shfl_xor_sync(0xffffffff, sum0, 2);
        sum1 += __shfl_xor_sync(0xffffffff, sum1, 1);
        sum1 += __shfl_xor_sync(0xffffffff, sum1, 2);
        l0 = l0 * al0 + sum0;  l1 = l1 * al1 + sum1;
        m0 = mn0;  m1 = mn1;
        #pragma unroll
        for (int ni = 0; ni < 8; ni++) {
            o[ni][0] *= al0; o[ni][1] *= al0;
            o[ni][2] *= al1; o[ni][3] *= al1;
        }

        // ---- O += P V (split, 3 passes) ----
        const uint32_t svh = st + 16384, svl = st + 24576;
        #pragma unroll
        for (int kk = 0; kk < 4; kk++) {
            uint32_t ph[4], pl[4];
            mk_pfrag(s[2*kk][0],   s[2*kk][1],   ph[0], pl[0]);
            mk_pfrag(s[2*kk][2],   s[2*kk][3],   ph[1], pl[1]);
            mk_pfrag(s[2*kk+1][0], s[2*kk+1][1], ph[2], pl[2]);
            mk_pfrag(s[2*kk+1][2], s[2*kk+1][3], ph[3], pl[3]);
            #pragma unroll
            for (int np = 0; np < 4; np++) {
                uint32_t off = SWZ128((kk*16 + kvb)*128 + np*32 + cbB);
                uint32_t v0, v1, v2, v3, u0, u1, u2, u3;
                LDSM_X4_TRANS(v0, v1, v2, v3, svh + off);
                LDSM_X4_TRANS(u0, u1, u2, u3, svl + off);
                uint32_t wh0[2] = {v0, v1}, wh1[2] = {v2, v3};
                uint32_t wl0[2] = {u0, u1}, wl1[2] = {u2, u3};
                MMA16816(o[2*np],   ph, wh0);
                MMA16816(o[2*np],   ph, wl0);
                MMA16816(o[2*np],   pl, wh0);
                MMA16816(o[2*np+1], ph, wh1);
                MMA16816(o[2*np+1], ph, wl1);
                MMA16816(o[2*np+1], pl, wh1);
            }
        }
    }

    // ---- epilogue: normalize, split, store ----
    float i0 = 1.f / l0, i1 = 1.f / l1;
    size_t r0 = qbase + wid*16 + g;
    size_t r1 = r0 + 8;
    #pragma unroll
    for (int ni = 0; ni < 8; ni++) {
        size_t col = hoff + ni*8 + tig*2;
        float f0 = o[ni][0]*i0, f1 = o[ni][1]*i0;
        float f2 = o[ni][2]*i1, f3 = o[ni][3]*i1;
        __nv_bfloat162 H, L;
        split_bf16(f0, H.x, L.x); split_bf16(f1, H.y, L.y);
        *(__nv_bfloat162*)(Ohi + r0*CDIM + col) = H;
        *(__nv_bfloat162*)(Olo + r0*CDIM + col) = L;
        split_bf16(f2, H.x, L.x); split_bf16(f3, H.y, L.y);
        *(__nv_bfloat162*)(Ohi + r1*CDIM + col) = H;
        *(__nv_bfloat162*)(Olo + r1*CDIM + col) = L;
    }
}

// ======================= launch ============================================
extern "C" void kernel_launch(void* const* d_in, const int* in_sizes, int n_in,
                              void* d_out, int out_size)
{
    const float* x    = (const float*)d_in[0];
    const float* ln1w = (const float*)d_in[2];
    const float* ln1b = (const float*)d_in[3];
    const float* ln2w = (const float*)d_in[4];
    const float* ln2b = (const float*)d_in[5];
    const float* wq   = (const float*)d_in[6];
    const float* bq   = (const float*)d_in[7];
    const float* wk   = (const float*)d_in[8];
    const float* bk   = (const float*)d_in[9];
    const float* wv   = (const float*)d_in[10];
    const float* bv   = (const float*)d_in[11];
    const float* wo   = (const float*)d_in[12];
    const float* bo   = (const float*)d_in[13];
    const float* w1   = (const float*)d_in[14];
    const float* b1   = (const float*)d_in[15];
    const float* w2   = (const float*)d_in[16];
    const float* b2   = (const float*)d_in[17];
    float* out = (float*)d_out;

    __nv_bfloat16 *hhi, *hlo, *qhi, *qlo, *khi, *klo, *vhi, *vlo;
    __nv_bfloat16 *ctxhi, *ctxlo, *h2hi, *h2lo, *ff1hi, *ff1lo;
    __nv_bfloat16 *wqh, *wql, *wkh, *wkl, *wvh, *wvl, *woh, *wol, *w1h, *w1l, *w2h, *w2l;
    float *x1;
    cudaGetSymbolAddress((void**)&hhi, g_h_hi);   cudaGetSymbolAddress((void**)&hlo, g_h_lo);
    cudaGetSymbolAddress((void**)&qhi, g_q_hi);   cudaGetSymbolAddress((void**)&qlo, g_q_lo);
    cudaGetSymbolAddress((void**)&khi, g_k_hi);   cudaGetSymbolAddress((void**)&klo, g_k_lo);
    cudaGetSymbolAddress((void**)&vhi, g_v_hi);   cudaGetSymbolAddress((void**)&vlo, g_v_lo);
    cudaGetSymbolAddress((void**)&ctxhi, g_ctx_hi); cudaGetSymbolAddress((void**)&ctxlo, g_ctx_lo);
    cudaGetSymbolAddress((void**)&x1,  g_x1);
    cudaGetSymbolAddress((void**)&h2hi, g_h2_hi); cudaGetSymbolAddress((void**)&h2lo, g_h2_lo);
    cudaGetSymbolAddress((void**)&ff1hi, g_ff1_hi); cudaGetSymbolAddress((void**)&ff1lo, g_ff1_lo);
    cudaGetSymbolAddress((void**)&wqh, g_wqT_hi); cudaGetSymbolAddress((void**)&wql, g_wqT_lo);
    cudaGetSymbolAddress((void**)&wkh, g_wkT_hi); cudaGetSymbolAddress((void**)&wkl, g_wkT_lo);
    cudaGetSymbolAddress((void**)&wvh, g_wvT_hi); cudaGetSymbolAddress((void**)&wvl, g_wvT_lo);
    cudaGetSymbolAddress((void**)&woh, g_woT_hi); cudaGetSymbolAddress((void**)&wol, g_woT_lo);
    cudaGetSymbolAddress((void**)&w1h, g_w1T_hi); cudaGetSymbolAddress((void**)&w1l, g_w1T_lo);
    cudaGetSymbolAddress((void**)&w2h, g_w2T_hi); cudaGetSymbolAddress((void**)&w2l, g_w2T_lo);

    cudaFuncSetAttribute(gemm_mma<1>, cudaFuncAttributeMaxDynamicSharedMemorySize, GEMM_SMEM);
    cudaFuncSetAttribute(gemm_mma<2>, cudaFuncAttributeMaxDynamicSharedMemorySize, GEMM_SMEM);
    cudaFuncSetAttribute(gemm_mma<3>, cudaFuncAttributeMaxDynamicSharedMemorySize, GEMM_SMEM);
    cudaFuncSetAttribute(flash_attn_tc, cudaFuncAttributeMaxDynamicSharedMemorySize, ATT_SMEM);

    dim3 tb(32, 8);
    wsplitT_kernel<<<dim3(CDIM/32, CDIM/32), tb>>>(wq, wqh, wql, CDIM, CDIM);
    wsplitT_kernel<<<dim3(CDIM/32, CDIM/32), tb>>>(wk, wkh, wkl, CDIM, CDIM);
    wsplitT_kernel<<<dim3(CDIM/32, CDIM/32), tb>>>(wv, wvh, wvl, CDIM, CDIM);
    wsplitT_kernel<<<dim3(CDIM/32, CDIM/32), tb>>>(wo, woh, wol, CDIM, CDIM);
    wsplitT_kernel<<<dim3(FFDIM/32, CDIM/32), tb>>>(w1, w1h, w1l, CDIM, FFDIM);
    wsplitT_kernel<<<dim3(CDIM/32, FFDIM/32), tb>>>(w2, w2h, w2l, FFDIM, CDIM);

    dim3 gproj(CDIM/128, ROWS/128);    // (8, 64)
    dim3 gff1 (FFDIM/128, ROWS/128);   // (32, 64)

    // 1) LN1 -> h (bf16 split)
    ln_kernel<<<ROWS, 256>>>(x, ln1w, ln1b, hhi, hlo);
    // 2) QKV -> bf16 split q/k/v
    gemm_mma<3><<<gproj, 256, GEMM_SMEM>>>(hhi, hlo, wqh, wql, bq, nullptr, nullptr, qhi, qlo, CDIM, CDIM);
    gemm_mma<3><<<gproj, 256, GEMM_SMEM>>>(hhi, hlo, wkh, wkl, bk, nullptr, nullptr, khi, klo, CDIM, CDIM);
    gemm_mma<3><<<gproj, 256, GEMM_SMEM>>>(hhi, hlo, wvh, wvl, bv, nullptr, nullptr, vhi, vlo, CDIM, CDIM);
    // 3) tensor-core flash attention -> ctx (bf16 split)
    flash_attn_tc<<<dim3(SEQ/64, NHEAD, BATCH), 128, ATT_SMEM>>>(qhi, qlo, khi, klo, vhi, vlo, ctxhi, ctxlo);
    // 4) O-proj + residual -> x1 (fp32)
    gemm_mma<1><<<gproj, 256, GEMM_SMEM>>>(ctxhi, ctxlo, woh, wol, bo, x, x1, nullptr, nullptr, CDIM, CDIM);
    // 5) LN2 -> h2 (bf16 split)
    ln_kernel<<<ROWS, 256>>>(x1, ln2w, ln2b, h2hi, h2lo);
    // 6) FFN1 + GELU -> ff1 (bf16 split)
    gemm_mma<2><<<gff1, 256, GEMM_SMEM>>>(h2hi, h2lo, w1h, w1l, b1, nullptr, nullptr, ff1hi, ff1lo, CDIM, FFDIM);
    // 7) FFN2 + residual -> out (fp32)
    gemm_mma<1><<<gproj, 256, GEMM_SMEM>>>(ff1hi, ff1lo, w2h, w2l, b2, x1, out, nullptr, nullptr, FFDIM, CDIM);
}